// round 5
// baseline (speedup 1.0000x reference)
#include <cuda_runtime.h>
#include <cuda_fp16.h>

#define N_NODES   50000
#define N_EDGES   1600000
#define NUM_GRAPHS 64
#define F   64
#define FIN 128
#define NB_SCAN   196

#define FILL_BLKS  6250        // ceil(N_EDGES/256)
#define GEMM_BLKS  782         // ceil(N_NODES/64)
#define RED_BLKS   98          // ceil(N_NODES/512)

// ---------------- scratch ----------------
__device__ __align__(16) __half g_h [N_NODES * F];
__device__ __align__(16) __half g_o1[N_NODES * F];
__device__ __align__(16) __half g_A [N_NODES * F];
__device__ __align__(16) float  g_G[NUM_GRAPHS * F];
__device__ int      g_is64;
__device__ int      g_deg[N_NODES];
__device__ int      g_rowptr[N_NODES + 1];
__device__ int      g_cursor[N_NODES];
__device__ __align__(16) unsigned g_csr[N_EDGES + 4];   // (src<<16)|half(w), +pad for uint4 reads

// ---------------- zero meta + dtype detect ----------------
__global__ void k_zero_meta(const int* __restrict__ ei32) {
    int i = blockIdx.x * 256 + threadIdx.x;
    if (i < N_NODES) g_deg[i] = 0;
    if (i < NUM_GRAPHS * F) g_G[i] = 0.f;
    if (i == 0) {
        int all0 = 1;
        for (int j = 0; j < 64; j++)
            if (ei32[2 * j + 1] != 0) { all0 = 0; break; }
        g_is64 = all0;
    }
}

// ---------------- degree histogram (2 edges/thread, vector loads) ----------------
__global__ void k_hist(const int* __restrict__ ei32) {
    int e0 = (blockIdx.x * blockDim.x + threadIdx.x) * 2;
    if (e0 >= N_EDGES) return;
    if (g_is64) {
        int4 v = *(const int4*)&ei32[2 * N_EDGES + 2 * e0];
        atomicAdd(&g_deg[v.x], 1);
        if (e0 + 1 < N_EDGES) atomicAdd(&g_deg[v.z], 1);
    } else {
        int2 v = *(const int2*)&ei32[N_EDGES + e0];
        atomicAdd(&g_deg[v.x], 1);
        if (e0 + 1 < N_EDGES) atomicAdd(&g_deg[v.y], 1);
    }
}

// ---------------- single-block scan: rowptr/cursor = exclusive_scan(deg) ----------------
__global__ void k_scan() {
    __shared__ int warpsum[32];
    int tid = threadIdx.x;
    const int CH = 49;                       // 1024*49 = 50176 >= 50000
    int start = tid * CH;
    int end   = min(start + CH, N_NODES);
    int s = 0;
    for (int i = start; i < end; i++) s += g_deg[i];
    int lane = tid & 31, w = tid >> 5;
    int v = s;
#pragma unroll
    for (int o = 1; o < 32; o <<= 1) {
        int t = __shfl_up_sync(0xffffffffu, v, o);
        if (lane >= o) v += t;
    }
    if (lane == 31) warpsum[w] = v;
    __syncthreads();
    if (w == 0) {
        int wv = warpsum[lane];
#pragma unroll
        for (int o = 1; o < 32; o <<= 1) {
            int t = __shfl_up_sync(0xffffffffu, wv, o);
            if (lane >= o) wv += t;
        }
        warpsum[lane] = wv;
    }
    __syncthreads();
    int excl = v - s + (w ? warpsum[w - 1] : 0);
    int run = excl;
    for (int i = start; i < end; i++) {
        g_rowptr[i] = run;
        g_cursor[i] = run;
        run += g_deg[i];
    }
    if (tid == 0) g_rowptr[N_NODES] = N_EDGES;
}

// ---------------- fused: CSR fill (blocks < FILL_BLKS)  ||  GEMM1 (rest) ----------------
// GEMM1: g_h = half(x[50000,128] @ W1[128,64]); 256 thr, tile 64x64, thread 4x4.
__global__ void k_fill_gemm1(const int* __restrict__ ei32, const float* __restrict__ ew,
                             const float* __restrict__ X, const float* __restrict__ W) {
    __shared__ float sx[64 * 68];
    __shared__ float sw[64 * 68];
    int tid = threadIdx.x;

    if (blockIdx.x < FILL_BLKS) {
        int e = blockIdx.x * 256 + tid;
        if (e >= N_EDGES) return;
        int is64 = g_is64;
        int s, d;
        if (is64) { s = ei32[2 * e]; d = ei32[2 * N_EDGES + 2 * e]; }
        else      { s = ei32[e];     d = ei32[N_EDGES + e]; }
        int pos = atomicAdd(&g_cursor[d], 1);
        unsigned hw = (unsigned)__half_as_ushort(__float2half_rn(__ldg(&ew[e])));
        g_csr[pos] = ((unsigned)s << 16) | hw;
        return;
    }

    // ---- GEMM1 ----
    int row0 = (blockIdx.x - FILL_BLKS) * 64;
    int tx = tid & 15;      // col group: cols tx*4..+3
    int ty = tid >> 4;      // row group: rows ty*4..+3

    float acc[4][4];
#pragma unroll
    for (int i = 0; i < 4; i++)
#pragma unroll
        for (int j = 0; j < 4; j++) acc[i][j] = 0.f;

    for (int kt = 0; kt < FIN; kt += 64) {
        __syncthreads();
        for (int i = tid; i < 64 * 64; i += 256) {
            int r = i >> 6, k = i & 63;
            float v = (row0 + r < N_NODES) ? X[(size_t)(row0 + r) * FIN + kt + k] : 0.f;
            sx[k * 68 + r] = v;
        }
        for (int i = tid; i < 64 * 64; i += 256) {
            int k = i >> 6, c = i & 63;
            sw[k * 68 + c] = W[(size_t)(kt + k) * F + c];
        }
        __syncthreads();
#pragma unroll
        for (int k = 0; k < 64; k++) {
            float4 xa = *(const float4*)&sx[k * 68 + ty * 4];
            float4 wa = *(const float4*)&sw[k * 68 + tx * 4];
            float xr[4] = {xa.x, xa.y, xa.z, xa.w};
            float wc[4] = {wa.x, wa.y, wa.z, wa.w};
#pragma unroll
            for (int i = 0; i < 4; i++)
#pragma unroll
                for (int j = 0; j < 4; j++)
                    acc[i][j] += xr[i] * wc[j];
        }
    }

#pragma unroll
    for (int i = 0; i < 4; i++) {
        int r = row0 + ty * 4 + i;
        if (r >= N_NODES) continue;
        __half2 o[2];
        o[0] = __floats2half2_rn(acc[i][0], acc[i][1]);
        o[1] = __floats2half2_rn(acc[i][2], acc[i][3]);
        *(uint2*)&g_h[(size_t)r * F + tx * 4] = *(uint2*)o;
    }
}

// ---------------- fp16 accumulate helper ----------------
__device__ __forceinline__ void hacc8(float* acc, uint4 raw, float w) {
    __half2* h = (__half2*)&raw;
#pragma unroll
    for (int q = 0; q < 4; q++) {
        float2 f = __half22float2(h[q]);
        acc[2 * q]     += w * f.x;
        acc[2 * q + 1] += w * f.y;
    }
}

// ---------------- CSR gather: out[n] = post( sum_e w_e * in[src_e] ) ----------------
// 8 threads/node, 64 nodes per 512-thread block, 4096-edge smem tiles (uint4 staged).
__global__ void __launch_bounds__(512) k_gather(const __half* __restrict__ in,
                                                __half* __restrict__ out,
                                                const float* __restrict__ bias, int relu) {
    __shared__ __align__(16) unsigned tile[4096];
    int tid   = threadIdx.x;
    int node0 = blockIdx.x * 64;
    int n     = node0 + (tid >> 3);
    int sub   = (tid & 7) * 8;
    int hi_node = min(node0 + 64, N_NODES);

    int e_begin = __ldg(&g_rowptr[node0]);
    int e_end   = __ldg(&g_rowptr[hi_node]);
    int my_s, my_e;
    if (n < N_NODES) { my_s = __ldg(&g_rowptr[n]); my_e = __ldg(&g_rowptr[n + 1]); }
    else             { my_s = my_e = 0; }

    float acc[8];
#pragma unroll
    for (int j = 0; j < 8; j++) acc[j] = 0.f;

    int base0 = e_begin & ~3;               // align for uint4 staging
    for (int base = base0; base < e_end; base += 4096) {
        int cnt = min(4096, e_end - base);
        __syncthreads();
        int q = (cnt + 3) >> 2;
        for (int i = tid; i < q; i += 512)
            ((uint4*)tile)[i] = *(const uint4*)&g_csr[base + 4 * i];
        __syncthreads();

        int lo = max(my_s, base);
        int hi = min(my_e, base + cnt);
        int e = lo;
        // head to 4-alignment
        for (; e < hi && (e & 3); e++) {
            unsigned p = tile[e - base];
            uint4 r = *(const uint4*)&in[(size_t)(p >> 16) * F + sub];
            hacc8(acc, r, __half2float(__ushort_as_half((unsigned short)(p & 0xffffu))));
        }
        for (; e + 4 <= hi; e += 4) {
            uint4 p4 = *(const uint4*)&tile[e - base];
            uint4 r0 = *(const uint4*)&in[(size_t)(p4.x >> 16) * F + sub];
            uint4 r1 = *(const uint4*)&in[(size_t)(p4.y >> 16) * F + sub];
            uint4 r2 = *(const uint4*)&in[(size_t)(p4.z >> 16) * F + sub];
            uint4 r3 = *(const uint4*)&in[(size_t)(p4.w >> 16) * F + sub];
            hacc8(acc, r0, __half2float(__ushort_as_half((unsigned short)(p4.x & 0xffffu))));
            hacc8(acc, r1, __half2float(__ushort_as_half((unsigned short)(p4.y & 0xffffu))));
            hacc8(acc, r2, __half2float(__ushort_as_half((unsigned short)(p4.z & 0xffffu))));
            hacc8(acc, r3, __half2float(__ushort_as_half((unsigned short)(p4.w & 0xffffu))));
        }
        for (; e < hi; e++) {
            unsigned p = tile[e - base];
            uint4 r = *(const uint4*)&in[(size_t)(p >> 16) * F + sub];
            hacc8(acc, r, __half2float(__ushort_as_half((unsigned short)(p & 0xffffu))));
        }
    }

    if (n < N_NODES) {
        if (bias) {
#pragma unroll
            for (int j = 0; j < 8; j++) acc[j] += __ldg(&bias[sub + j]);
        }
        if (relu) {
#pragma unroll
            for (int j = 0; j < 8; j++) acc[j] = fmaxf(acc[j], 0.f);
        }
        __half2 o[4];
#pragma unroll
        for (int q2 = 0; q2 < 4; q2++)
            o[q2] = __floats2half2_rn(acc[2 * q2], acc[2 * q2 + 1]);
        *(uint4*)&out[(size_t)n * F + sub] = *(uint4*)o;
    }
}

// ---------------- fused: GEMM2 (blocks < GEMM_BLKS) || segment reduce (rest) ----------------
__global__ void k_gemm2_reduce(const float* __restrict__ W, const float* __restrict__ bias,
                               float* __restrict__ out, const int* __restrict__ b32) {
    __shared__ float sx[64 * 68];
    __shared__ float sw[64 * 68];
    int tid = threadIdx.x;

    if (blockIdx.x >= GEMM_BLKS) {
        // ---- segment reduce: g_G += segsum over 512 nodes ----
        int is64 = g_is64;
        int c  = tid & 63;
        int rl = tid >> 6;
        int base = (blockIdx.x - GEMM_BLKS) * 512;
        float acc = 0.f;
        int cur = -1;
        for (int j = 0; j < 128; j++) {
            int r = base + rl + (j << 2);
            if (r >= N_NODES) break;
            int g = is64 ? b32[2 * r] : b32[r];
            if (g != cur) {
                if (cur >= 0) atomicAdd(&g_G[cur * F + c], acc);
                cur = g; acc = 0.f;
            }
            acc += __half2float(g_A[(size_t)r * F + c]);
        }
        if (cur >= 0) atomicAdd(&g_G[cur * F + c], acc);
        return;
    }

    // ---- GEMM2: out = A(half) @ W2 + b2 ----
    int row0 = blockIdx.x * 64;
    int tx = tid & 15;
    int ty = tid >> 4;

    for (int t = tid; t < 512; t += 256) {
        int r = t >> 3, k8 = (t & 7) * 8;
        uint4 raw;
        if (row0 + r < N_NODES) raw = *(const uint4*)&g_A[(size_t)(row0 + r) * F + k8];
        else raw = make_uint4(0, 0, 0, 0);
        __half2* h = (__half2*)&raw;
#pragma unroll
        for (int q = 0; q < 4; q++) {
            float2 f = __half22float2(h[q]);
            sx[(k8 + 2 * q) * 68 + r]     = f.x;
            sx[(k8 + 2 * q + 1) * 68 + r] = f.y;
        }
    }
    for (int i = tid; i < 64 * 64; i += 256) {
        int k = i >> 6, c = i & 63;
        sw[k * 68 + c] = W[(size_t)k * F + c];
    }
    __syncthreads();

    float acc[4][4];
#pragma unroll
    for (int i = 0; i < 4; i++)
#pragma unroll
        for (int j = 0; j < 4; j++) acc[i][j] = 0.f;

#pragma unroll
    for (int k = 0; k < 64; k++) {
        float4 xa = *(const float4*)&sx[k * 68 + ty * 4];
        float4 wa = *(const float4*)&sw[k * 68 + tx * 4];
        float xr[4] = {xa.x, xa.y, xa.z, xa.w};
        float wc[4] = {wa.x, wa.y, wa.z, wa.w};
#pragma unroll
        for (int i = 0; i < 4; i++)
#pragma unroll
            for (int j = 0; j < 4; j++)
                acc[i][j] += xr[i] * wc[j];
    }

    float bb[4];
#pragma unroll
    for (int j = 0; j < 4; j++) bb[j] = bias[tx * 4 + j];

#pragma unroll
    for (int i = 0; i < 4; i++) {
        int r = row0 + ty * 4 + i;
        if (r >= N_NODES) continue;
        float4 o0 = make_float4(acc[i][0] + bb[0], acc[i][1] + bb[1],
                                acc[i][2] + bb[2], acc[i][3] + bb[3]);
        *(float4*)&out[(size_t)r * F + tx * 4] = o0;
    }
}

// ---------------- graph_embed = G @ W3 + counts*b3 ----------------
__global__ void k_gout(const int* __restrict__ b32, const float* __restrict__ W3,
                       const float* __restrict__ b3, float* __restrict__ out) {
    __shared__ float sG[F];
    __shared__ int scount;
    int g = blockIdx.x, j = threadIdx.x;
    sG[j] = g_G[g * F + j];
    if (j == 0) {
        int is64 = g_is64;
        int lo = 0, hi = N_NODES;
        while (lo < hi) { int m = (lo + hi) >> 1; int v = is64 ? b32[2 * m] : b32[m]; if (v < g) lo = m + 1; else hi = m; }
        int a = lo;
        lo = 0; hi = N_NODES;
        while (lo < hi) { int m = (lo + hi) >> 1; int v = is64 ? b32[2 * m] : b32[m]; if (v < g + 1) lo = m + 1; else hi = m; }
        scount = lo - a;
    }
    __syncthreads();
    float acc = (float)scount * b3[j];
#pragma unroll 8
    for (int k = 0; k < F; k++) acc += sG[k] * W3[k * F + j];
    out[g * F + j] = acc;
}

extern "C" void kernel_launch(void* const* d_in, const int* in_sizes, int n_in,
                              void* d_out, int out_size) {
    const float* x    = (const float*)d_in[0];
    const int*   ei32 = (const int*)d_in[1];
    const float* ew   = (const float*)d_in[2];
    const int*   b32  = (const int*)d_in[3];
    const float* W1   = (const float*)d_in[4];
    const float* b1   = (const float*)d_in[5];
    const float* W2   = (const float*)d_in[6];
    const float* b2   = (const float*)d_in[7];
    const float* b3   = (const float*)d_in[9];
    const float* W3   = (const float*)d_in[8];
    float* out = (float*)d_out;

    __half *h, *o1, *A;
    cudaGetSymbolAddress((void**)&h,  g_h);
    cudaGetSymbolAddress((void**)&o1, g_o1);
    cudaGetSymbolAddress((void**)&A,  g_A);

    k_zero_meta<<<NB_SCAN, 256>>>(ei32);
    k_hist<<<(N_EDGES / 2 + 255) / 256, 256>>>(ei32);
    k_scan<<<1, 1024>>>();
    k_fill_gemm1<<<FILL_BLKS + GEMM_BLKS, 256>>>(ei32, ew, x, W1);
    k_gather<<<GEMM_BLKS, 512>>>(h, o1, b1, 1);
    k_gather<<<GEMM_BLKS, 512>>>(o1, A, nullptr, 0);
    k_gemm2_reduce<<<GEMM_BLKS + RED_BLKS, 256>>>(W2, b2, out, b32);
    k_gout<<<NUM_GRAPHS, F>>>(b32, W3, b3, out + (size_t)N_NODES * F);
}